// round 15
// baseline (speedup 1.0000x reference)
#include <cuda_runtime.h>

#define BATCH 2
#define NSEQ 4096
#define CDIM 128
#define HEADS 4
#define HD 32
#define C2 256
#define MTOT (BATCH*NSEQ)
#define BH (BATCH*HEADS)
#define NROWS (BH*NSEQ)
#define SPLITS 2
#define TILES_PER_SPLIT (NSEQ/32/SPLITS)   // 64
#define KP 40
#define QSCALE (0.17677669529663687f * 1.4426950408889634f)

// pre-split weight table offsets (rows of 128)
#define WOFF_QKV   0            // [q(128); kv(256)]
#define WOFF_PROJ  49152
#define WOFF_CONV1 65536
#define WOFF_CONV4 98304
#define WTOTAL     114688

typedef unsigned long long u64;
typedef unsigned short u16;

// ---------------- scratch ----------------
__device__ float g_xmid [MTOT*CDIM];
__device__ float g_c1   [MTOT*C2];
__device__ float g_gate [MTOT*CDIM];
__device__ float g_pacc [SPLITS*NROWS*HD];
__device__ float g_pl   [SPLITS*NROWS];
__device__ float g_stats1[MTOT*2];
__device__ float g_stats2[MTOT*2];
__device__ float g_wh   [WTOTAL];    // tf32-rounded weights (hi)
__device__ float g_wl   [WTOTAL];    // tf32 residual (lo)
__device__ __align__(16) u16 g_qh[BH*NSEQ*HD];
__device__ __align__(16) u16 g_kh[BH*NSEQ*HD];
__device__ __align__(16) u16 g_vT[BH*NSEQ*HD];

// ---------------- helpers ----------------
__device__ __forceinline__ float ex2(float x) {
    float r; asm("ex2.approx.f32 %0, %1;" : "=f"(r) : "f"(x)); return r;
}
__device__ __forceinline__ unsigned cvt_tf32(float x) {
    unsigned r; asm("cvt.rna.tf32.f32 %0, %1;" : "=r"(r) : "f"(x)); return r;
}
__device__ __forceinline__ float tf32r(float x) { return __uint_as_float(cvt_tf32(x)); }
__device__ __forceinline__ unsigned bf16x2(float hi, float lo) {
    unsigned r;
    asm("cvt.rn.satfinite.bf16x2.f32 %0, %1, %2;" : "=r"(r) : "f"(hi), "f"(lo));
    return r;
}
__device__ __forceinline__ void mma_tf32(float* d,
    unsigned a0, unsigned a1, unsigned a2, unsigned a3, unsigned b0, unsigned b1) {
    asm("mma.sync.aligned.m16n8k8.row.col.f32.tf32.tf32.f32 "
        "{%0,%1,%2,%3}, {%4,%5,%6,%7}, {%8,%9}, {%0,%1,%2,%3};"
        : "+f"(d[0]), "+f"(d[1]), "+f"(d[2]), "+f"(d[3])
        : "r"(a0), "r"(a1), "r"(a2), "r"(a3), "r"(b0), "r"(b1));
}
__device__ __forceinline__ void mma_bf16(float* d,
    unsigned a0, unsigned a1, unsigned a2, unsigned a3, unsigned b0, unsigned b1) {
    asm("mma.sync.aligned.m16n8k16.row.col.f32.bf16.bf16.f32 "
        "{%0,%1,%2,%3}, {%4,%5,%6,%7}, {%8,%9}, {%0,%1,%2,%3};"
        : "+f"(d[0]), "+f"(d[1]), "+f"(d[2]), "+f"(d[3])
        : "r"(a0), "r"(a1), "r"(a2), "r"(a3), "r"(b0), "r"(b1));
}

// ---------------- LN stats (+ fused one-time weight split on WHICH==1) ----------------
template<int WHICH>
__global__ void __launch_bounds__(256) ln_stats(const float* __restrict__ xin,
                                                const float* __restrict__ q_w,
                                                const float* __restrict__ kv_w,
                                                const float* __restrict__ proj_w,
                                                const float* __restrict__ conv1_w,
                                                const float* __restrict__ conv4_w) {
    if (WHICH == 1) {
        const int wi = blockIdx.x*256 + threadIdx.x;   // 262144 threads >= WTOTAL
        if (wi < WTOTAL) {
            float v;
            if      (wi < 16384) v = q_w[wi];
            else if (wi < 49152) v = kv_w[wi - 16384];
            else if (wi < 65536) v = proj_w[wi - 49152];
            else if (wi < 98304) v = conv1_w[wi - 65536];
            else                 v = conv4_w[wi - 98304];
            float h = tf32r(v);
            g_wh[wi] = h;
            g_wl[wi] = tf32r(v - h);
        }
    }
    const float* in = (WHICH == 1) ? xin : g_xmid;
    float*       st = (WHICH == 1) ? g_stats1 : g_stats2;
    const int row = blockIdx.x*8 + (threadIdx.x >> 5);
    const int lane = threadIdx.x & 31;
    float4 v = *(const float4*)(in + (size_t)row*CDIM + lane*4);
    float s = (v.x + v.y) + (v.z + v.w);
    #pragma unroll
    for (int o = 16; o; o >>= 1) s += __shfl_xor_sync(0xffffffffu, s, o);
    const float mu = s * (1.0f/128.0f);
    float dx = v.x-mu, dy = v.y-mu, dz = v.z-mu, dw = v.w-mu;
    float q = (dx*dx + dy*dy) + (dz*dz + dw*dw);
    #pragma unroll
    for (int o = 16; o; o >>= 1) q += __shfl_xor_sync(0xffffffffu, q, o);
    if (lane == 0)
        *(float2*)&st[row*2] = make_float2(mu, rsqrtf(q*(1.0f/128.0f) + 1e-5f));
}

// ---------------- GEMM: tile m64 x o64, 4 warps, K=128 in 8 chunks; pre-split W ----------------
// MODE 0: A=x(arg)+LN1, single tf32, bf16 out (Q scale folded)
// MODE 1: A = split-KV reduce of g_pacc/g_pl (fused), 3xTF32, +bias +resid(x) -> g_xmid
// MODE 2: A=g_xmid+LN2, 3xTF32, +bias -> g_c1
// MODE 3: A=g_gate,     3xTF32, +bias +resid(g_xmid) -> out_ext
template<int MODE>
__global__ void __launch_bounds__(128) gemm_mma(const float* __restrict__ Aext,
                                                const float* __restrict__ bias,
                                                const float* __restrict__ lnw,
                                                const float* __restrict__ lnb,
                                                const float* __restrict__ resid_ext,
                                                float* __restrict__ out_ext) {
    constexpr bool EX = (MODE != 0);
    constexpr bool LN = (MODE == 0 || MODE == 2);
    constexpr int  WOFF = (MODE == 0) ? WOFF_QKV :
                          (MODE == 1) ? WOFF_PROJ :
                          (MODE == 2) ? WOFF_CONV1 : WOFF_CONV4;
    const float* A;
    if (MODE == 0)      A = Aext;
    else if (MODE == 1) A = nullptr;
    else if (MODE == 2) A = g_xmid;
    else                A = g_gate;
    const float* stats = (MODE == 0) ? g_stats1 : g_stats2;

    __shared__ float Ah[64][20], Wh[64][20];
    __shared__ float Al[EX ? 64 : 1][20], Wl[EX ? 64 : 1][20];

    const int t = threadIdx.x;
    const int warp = t >> 5, lane = t & 31;
    const int g = lane >> 2, tg = lane & 3;
    const int m0 = blockIdx.x * 64;
    const int o0 = blockIdx.y * 64;
    const int lrow = t >> 2, c4 = (t & 3) * 4;

    float s[8][4] = {};

    float2 st0, st1;
    if (LN) {
        st0 = *(const float2*)(stats + (size_t)(m0 + lrow)*2);
        st1 = *(const float2*)(stats + (size_t)(m0 + lrow + 32)*2);
    }

    // MODE 1: per-row per-head 1/l
    int b0_ = 0, n0_ = 0, b1_ = 0, n1_ = 0;
    float invl0[4], invl1[4];
    float4 p0[SPLITS], p1[SPLITS];
    if (MODE == 1) {
        int m_ = m0 + lrow;  b0_ = m_ >> 12;  n0_ = m_ & 4095;
        int m2_ = m_ + 32;   b1_ = m2_ >> 12; n1_ = m2_ & 4095;
        #pragma unroll
        for (int h = 0; h < 4; ++h) {
            size_t r0 = (size_t)((b0_*4 + h)*4096 + n0_);
            size_t r1 = (size_t)((b1_*4 + h)*4096 + n1_);
            float l0 = g_pl[r0] + g_pl[(size_t)NROWS + r0];
            float l1 = g_pl[r1] + g_pl[(size_t)NROWS + r1];
            invl0[h] = 1.0f / l0;
            invl1[h] = 1.0f / l1;
        }
    }

    float4 a0, a1, w0h, w1h, w0l, w1l, lw, lb;

#define GEMM_LOAD(kc_) {                                                        \
        const int k0_ = (kc_)*16;                                               \
        if (MODE == 1) {                                                        \
            const int h_ = k0_ >> 5;                                            \
            const int hb_ = (k0_ & 31) + c4;                                    \
            const size_t r0_ = (size_t)((b0_*4 + h_)*4096 + n0_);               \
            const size_t r1_ = (size_t)((b1_*4 + h_)*4096 + n1_);               \
            _Pragma("unroll")                                                   \
            for (int s_ = 0; s_ < SPLITS; ++s_) {                               \
                p0[s_] = *(const float4*)(g_pacc + (((size_t)s_*NROWS + r0_)<<5) + hb_); \
                p1[s_] = *(const float4*)(g_pacc + (((size_t)s_*NROWS + r1_)<<5) + hb_); \
            }                                                                   \
        } else {                                                                \
            a0 = *(const float4*)(A + (size_t)(m0 + lrow     )*CDIM + k0_ + c4);\
            a1 = *(const float4*)(A + (size_t)(m0 + lrow + 32)*CDIM + k0_ + c4);\
        }                                                                       \
        w0h = *(const float4*)(g_wh + WOFF + (size_t)(o0 + lrow     )*CDIM + k0_ + c4); \
        w1h = *(const float4*)(g_wh + WOFF + (size_t)(o0 + lrow + 32)*CDIM + k0_ + c4); \
        if (EX) {                                                               \
            w0l = *(const float4*)(g_wl + WOFF + (size_t)(o0 + lrow     )*CDIM + k0_ + c4); \
            w1l = *(const float4*)(g_wl + WOFF + (size_t)(o0 + lrow + 32)*CDIM + k0_ + c4); \
        }                                                                       \
        if (LN) { lw = *(const float4*)(lnw + k0_ + c4);                        \
                  lb = *(const float4*)(lnb + k0_ + c4); } }

    GEMM_LOAD(0);

    #pragma unroll
    for (int kc = 0; kc < 8; ++kc) {
        if (kc) __syncthreads();
        if (MODE == 1) {
            const int h_ = kc >> 1;
            a0 = make_float4((p0[0].x+p0[1].x)*invl0[h_],
                             (p0[0].y+p0[1].y)*invl0[h_],
                             (p0[0].z+p0[1].z)*invl0[h_],
                             (p0[0].w+p0[1].w)*invl0[h_]);
            a1 = make_float4((p1[0].x+p1[1].x)*invl1[h_],
                             (p1[0].y+p1[1].y)*invl1[h_],
                             (p1[0].z+p1[1].z)*invl1[h_],
                             (p1[0].w+p1[1].w)*invl1[h_]);
        }
        if (LN) {
            a0.x = (a0.x - st0.x)*st0.y*lw.x + lb.x;
            a0.y = (a0.y - st0.x)*st0.y*lw.y + lb.y;
            a0.z = (a0.z - st0.x)*st0.y*lw.z + lb.z;
            a0.w = (a0.w - st0.x)*st0.y*lw.w + lb.w;
            a1.x = (a1.x - st1.x)*st1.y*lw.x + lb.x;
            a1.y = (a1.y - st1.x)*st1.y*lw.y + lb.y;
            a1.z = (a1.z - st1.x)*st1.y*lw.z + lb.z;
            a1.w = (a1.w - st1.x)*st1.y*lw.w + lb.w;
        }
        {
            float4 h0, h1;
            h0.x = tf32r(a0.x); h0.y = tf32r(a0.y); h0.z = tf32r(a0.z); h0.w = tf32r(a0.w);
            h1.x = tf32r(a1.x); h1.y = tf32r(a1.y); h1.z = tf32r(a1.z); h1.w = tf32r(a1.w);
            *(float4*)&Ah[lrow     ][c4] = h0;
            *(float4*)&Ah[lrow + 32][c4] = h1;
            if (EX) {
                float4 l0, l1;
                l0.x = tf32r(a0.x - h0.x); l0.y = tf32r(a0.y - h0.y);
                l0.z = tf32r(a0.z - h0.z); l0.w = tf32r(a0.w - h0.w);
                l1.x = tf32r(a1.x - h1.x); l1.y = tf32r(a1.y - h1.y);
                l1.z = tf32r(a1.z - h1.z); l1.w = tf32r(a1.w - h1.w);
                *(float4*)&Al[lrow     ][c4] = l0;
                *(float4*)&Al[lrow + 32][c4] = l1;
            }
            *(float4*)&Wh[lrow     ][c4] = w0h;
            *(float4*)&Wh[lrow + 32][c4] = w1h;
            if (EX) {
                *(float4*)&Wl[lrow     ][c4] = w0l;
                *(float4*)&Wl[lrow + 32][c4] = w1l;
            }
        }
        __syncthreads();
        if (kc < 7) GEMM_LOAD(kc + 1);

        #pragma unroll
        for (int ks = 0; ks < 2; ++ks) {
            const int k = ks * 8;
            const int mr = 16*warp;
            unsigned ah[4], al[4];
            ah[0] = __float_as_uint(Ah[mr + g    ][k + tg    ]);
            ah[1] = __float_as_uint(Ah[mr + g + 8][k + tg    ]);
            ah[2] = __float_as_uint(Ah[mr + g    ][k + tg + 4]);
            ah[3] = __float_as_uint(Ah[mr + g + 8][k + tg + 4]);
            if (EX) {
                al[0] = __float_as_uint(Al[mr + g    ][k + tg    ]);
                al[1] = __float_as_uint(Al[mr + g + 8][k + tg    ]);
                al[2] = __float_as_uint(Al[mr + g    ][k + tg + 4]);
                al[3] = __float_as_uint(Al[mr + g + 8][k + tg + 4]);
            }
            #pragma unroll
            for (int nt = 0; nt < 8; ++nt) {
                unsigned bh0 = __float_as_uint(Wh[8*nt + g][k + tg    ]);
                unsigned bh1 = __float_as_uint(Wh[8*nt + g][k + tg + 4]);
                mma_tf32(s[nt], ah[0], ah[1], ah[2], ah[3], bh0, bh1);
                if (EX) {
                    unsigned bl0 = __float_as_uint(Wl[8*nt + g][k + tg    ]);
                    unsigned bl1 = __float_as_uint(Wl[8*nt + g][k + tg + 4]);
                    mma_tf32(s[nt], ah[0], ah[1], ah[2], ah[3], bl0, bl1);
                    mma_tf32(s[nt], al[0], al[1], al[2], al[3], bh0, bh1);
                }
            }
        }
    }
#undef GEMM_LOAD

    // ---- epilogue ----
    const int mA = m0 + 16*warp + g;
    #pragma unroll
    for (int nt = 0; nt < 8; ++nt) {
        const int o = o0 + 8*nt + 2*tg;
        float2 v01 = make_float2(s[nt][0], s[nt][1]);
        float2 v23 = make_float2(s[nt][2], s[nt][3]);
        if (MODE == 0) {
            #pragma unroll
            for (int hf = 0; hf < 2; ++hf) {
                const int m = mA + 8*hf;
                float2 v = hf ? v23 : v01;
                const int b = m >> 12, n = m & 4095;
                if (o < 128) {
                    const int head = o >> 5, hd = o & 31;
                    *(unsigned*)&g_qh[((size_t)(b*HEADS + head)*NSEQ + n)*HD + hd] =
                        bf16x2(v.y*QSCALE, v.x*QSCALE);
                } else if (o < 256) {
                    const int oo = o - 128, head = oo >> 5, hd = oo & 31;
                    *(unsigned*)&g_kh[((size_t)(b*HEADS + head)*NSEQ + n)*HD + hd] =
                        bf16x2(v.y, v.x);
                } else {
                    const int oo = o - 256, head = oo >> 5, hd = oo & 31;
                    unsigned u = bf16x2(v.y, v.x);
                    size_t base = ((size_t)((b*HEADS + head)*128 + (n >> 5))*32 + hd)*32 + (n & 31);
                    g_vT[base]      = (u16)(u & 0xffffu);
                    g_vT[base + 32] = (u16)(u >> 16);
                }
            }
        } else if (MODE == 2) {
            float2 bv = *(const float2*)(bias + o);
            *(float2*)&g_c1[(size_t)mA*C2 + o] =
                make_float2(v01.x + bv.x, v01.y + bv.y);
            *(float2*)&g_c1[(size_t)(mA+8)*C2 + o] =
                make_float2(v23.x + bv.x, v23.y + bv.y);
        } else {
            const float* rs = (MODE == 1) ? resid_ext : g_xmid;
            float*       ds = (MODE == 1) ? g_xmid    : out_ext;
            float2 bv = *(const float2*)(bias + o);
            float2 r0 = *(const float2*)(rs + (size_t)mA*CDIM + o);
            float2 r1 = *(const float2*)(rs + (size_t)(mA+8)*CDIM + o);
            *(float2*)&ds[(size_t)mA*CDIM + o] =
                make_float2(v01.x + bv.x + r0.x, v01.y + bv.y + r0.y);
            *(float2*)&ds[(size_t)(mA+8)*CDIM + o] =
                make_float2(v23.x + bv.x + r1.x, v23.y + bv.y + r1.y);
        }
    }
}

// ---------------- Flash attention: bf16 m16n8k16, split-KV=2 ----------------
__global__ void __launch_bounds__(128, 4) attn_kernel() {
    const int bh    = blockIdx.x;
    const int split = blockIdx.z;
    const int t     = threadIdx.x;
    const int warp  = t >> 5;
    const int lane  = t & 31;
    const int g     = lane >> 2;
    const int tg    = lane & 3;

    const int q0 = blockIdx.y*128 + warp*32;
    const u16* Qb  = g_qh + ((size_t)bh*NSEQ + q0)*HD;
    const u16* Kb  = g_kh + ((size_t)bh*NSEQ + (size_t)split*(NSEQ/SPLITS))*HD;
    const u16* Vtb = g_vT + ((size_t)(bh*128 + split*TILES_PER_SPLIT))*1024;

    unsigned qf[2][2][4];
    #pragma unroll
    for (int mt = 0; mt < 2; ++mt)
        #pragma unroll
        for (int kk = 0; kk < 2; ++kk) {
            qf[mt][kk][0] = *(const unsigned*)&Qb[(16*mt + g    )*HD + 16*kk + 2*tg    ];
            qf[mt][kk][1] = *(const unsigned*)&Qb[(16*mt + g + 8)*HD + 16*kk + 2*tg    ];
            qf[mt][kk][2] = *(const unsigned*)&Qb[(16*mt + g    )*HD + 16*kk + 2*tg + 8];
            qf[mt][kk][3] = *(const unsigned*)&Qb[(16*mt + g + 8)*HD + 16*kk + 2*tg + 8];
        }

    __shared__ u16 Ks[2][32][KP];
    __shared__ u16 Vt[2][32][KP];

    float o[2][4][4] = {};
    float l[4] = {};

    const int lr  = t >> 2;
    const int lc8 = (t & 3) * 8;
    const float4* kptr = (const float4*)Kb  + t;
    const float4* vptr = (const float4*)Vtb + t;

    float4 ka = kptr[0];
    float4 va = vptr[0];

    for (int kt = 0; kt < TILES_PER_SPLIT; ++kt) {
        const int buf = kt & 1;
        *(float4*)&Ks[buf][lr][lc8] = ka;
        *(float4*)&Vt[buf][lr][lc8] = va;
        __syncthreads();

        if (kt + 1 < TILES_PER_SPLIT) {
            ka = kptr[(kt+1)*128];
            va = vptr[(kt+1)*128];
        }

        float s[2][4][4] = {};
        #pragma unroll
        for (int nt = 0; nt < 4; ++nt) {
            #pragma unroll
            for (int kk = 0; kk < 2; ++kk) {
                unsigned b0 = *(const unsigned*)&Ks[buf][8*nt + g][16*kk + 2*tg    ];
                unsigned b1 = *(const unsigned*)&Ks[buf][8*nt + g][16*kk + 2*tg + 8];
                mma_bf16(s[0][nt], qf[0][kk][0], qf[0][kk][1], qf[0][kk][2], qf[0][kk][3], b0, b1);
                mma_bf16(s[1][nt], qf[1][kk][0], qf[1][kk][1], qf[1][kk][2], qf[1][kk][3], b0, b1);
            }
        }

        unsigned pk[2][4][2];
        #pragma unroll
        for (int nt = 0; nt < 4; ++nt)
            #pragma unroll
            for (int mt = 0; mt < 2; ++mt) {
                float e0 = ex2(s[mt][nt][0]);
                float e1 = ex2(s[mt][nt][1]);
                float e2 = ex2(s[mt][nt][2]);
                float e3 = ex2(s[mt][nt][3]);
                l[2*mt]   += e0 + e1;
                l[2*mt+1] += e2 + e3;
                pk[mt][nt][0] = bf16x2(e1, e0);
                pk[mt][nt][1] = bf16x2(e3, e2);
            }

        #pragma unroll
        for (int kk2 = 0; kk2 < 2; ++kk2) {
            #pragma unroll
            for (int nd = 0; nd < 4; ++nd) {
                unsigned b0 = *(const unsigned*)&Vt[buf][8*nd + g][16*kk2 + 2*tg    ];
                unsigned b1 = *(const unsigned*)&Vt[buf][8*nd + g][16*kk2 + 2*tg + 8];
                #pragma unroll
                for (int mt = 0; mt < 2; ++mt)
                    mma_bf16(o[mt][nd],
                             pk[mt][2*kk2][0], pk[mt][2*kk2][1],
                             pk[mt][2*kk2+1][0], pk[mt][2*kk2+1][1],
                             b0, b1);
            }
        }
    }

    #pragma unroll
    for (int i = 0; i < 4; ++i) {
        l[i] += __shfl_xor_sync(0xffffffffu, l[i], 1);
        l[i] += __shfl_xor_sync(0xffffffffu, l[i], 2);
    }

    #pragma unroll
    for (int mt = 0; mt < 2; ++mt) {
        const size_t row = (size_t)bh*NSEQ + q0 + 16*mt + g;
        float* base0 = g_pacc + ((size_t)split*NROWS + row)*HD;
        float* base1 = base0 + 8*HD;
        #pragma unroll
        for (int nd = 0; nd < 4; ++nd) {
            *(float2*)(base0 + 8*nd + 2*tg) = make_float2(o[mt][nd][0], o[mt][nd][1]);
            *(float2*)(base1 + 8*nd + 2*tg) = make_float2(o[mt][nd][2], o[mt][nd][3]);
        }
        if (tg == 0) {
            g_pl[(size_t)split*NROWS + row    ] = l[2*mt];
            g_pl[(size_t)split*NROWS + row + 8] = l[2*mt+1];
        }
    }
}

// ---------------- dw 3x3 + 5x5 + gate: spatially tiled, smem halo ----------------
__global__ void __launch_bounds__(256) dw_gate_kernel(const float* __restrict__ w33,
                                                      const float* __restrict__ b33,
                                                      const float* __restrict__ w55,
                                                      const float* __restrict__ b55) {
    __shared__ float sIn[144][64];
    __shared__ float sw3[64][9];
    __shared__ float sw5[64][25];
    __shared__ float sbb[64];

    const int c   = threadIdx.x;
    const int py  = threadIdx.y;
    const int tid = py*32 + c;
    const int ca0 = blockIdx.y * 32;
    const int bz  = blockIdx.z;
    const int ty0 = (blockIdx.x >> 3) * 8;
    const int tx0 = (blockIdx.x & 7) * 8;

    for (int i = tid; i < 64*9; i += 256) {
        int s = i / 9, k = i - s*9;
        int gc = (s < 32) ? (ca0 + s) : (128 + ca0 + s - 32);
        sw3[s][k] = w33[gc*9 + k];
    }
    for (int i = tid; i < 64*25; i += 256) {
        int s = i / 25, k = i - s*25;
        int gc = (s < 32) ? (ca0 + s) : (128 + ca0 + s - 32);
        sw5[s][k] = w55[gc*25 + k];
    }
    if (tid < 64) {
        int gc = (tid < 32) ? (ca0 + tid) : (128 + ca0 + tid - 32);
        sbb[tid] = b33[gc] + b55[gc];
    }

    const float* cbase = g_c1 + (size_t)bz*NSEQ*C2;
    for (int i = tid; i < 2304; i += 256) {
        int px = i >> 4, c4 = i & 15;
        int hy = ty0 + (px/12) - 2, hx = tx0 + (px - (px/12)*12) - 2;
        float4 v = make_float4(0.f, 0.f, 0.f, 0.f);
        if (hy >= 0 && hy < 64 && hx >= 0 && hx < 64) {
            int gc = (c4 < 8) ? (ca0 + c4*4) : (128 + ca0 + (c4-8)*4);
            v = *(const float4*)(cbase + (size_t)(hy*64 + hx)*C2 + gc);
        }
        *(float4*)&sIn[px][c4*4] = v;
    }
    __syncthreads();

    float w5a[25], w5g[25];
    #pragma unroll
    for (int k = 0; k < 25; ++k) { w5a[k] = sw5[c][k]; w5g[k] = sw5[32+c][k]; }
    float w3a[9], w3g[9];
    #pragma unroll
    for (int k = 0; k < 9; ++k)  { w3a[k] = sw3[c][k]; w3g[k] = sw3[32+c][k]; }
    const float ba = sbb[c], bg = sbb[32+c];

    float* gout = g_gate + ((size_t)bz*NSEQ + (ty0+py)*64 + tx0)*CDIM + ca0 + c;

    #pragma unroll
    for (int x = 0; x < 8; ++x) {
        const int p0 = (py+2)*12 + (x+2);
        float a = ba + sIn[p0][c];
        float g = bg + sIn[p0][32+c];
        #pragma unroll
        for (int dy = -2; dy <= 2; ++dy) {
            #pragma unroll
            for (int dx = -2; dx <= 2; ++dx) {
                const int pp = p0 + dy*12 + dx;
                const float va = sIn[pp][c];
                const float vg = sIn[pp][32+c];
                const int i5 = (dy+2)*5 + (dx+2);
                a = fmaf(va, w5a[i5], a);
                g = fmaf(vg, w5g[i5], g);
                if (dy >= -1 && dy <= 1 && dx >= -1 && dx <= 1) {
                    const int i3 = (dy+1)*3 + (dx+1);
                    a = fmaf(va, w3a[i3], a);
                    g = fmaf(vg, w3g[i3], g);
                }
            }
        }
        gout[x*CDIM] = a * g;
    }
}

// ---------------- launch ----------------
extern "C" void kernel_launch(void* const* d_in, const int* in_sizes, int n_in,
                              void* d_out, int out_size) {
    (void)in_sizes; (void)n_in; (void)out_size;
    const float* x       = (const float*)d_in[0];
    const float* ln1_w   = (const float*)d_in[3];
    const float* ln1_b   = (const float*)d_in[4];
    const float* q_w     = (const float*)d_in[5];
    const float* kv_w    = (const float*)d_in[6];
    const float* proj_w  = (const float*)d_in[7];
    const float* proj_b  = (const float*)d_in[8];
    const float* ln2_w   = (const float*)d_in[9];
    const float* ln2_b   = (const float*)d_in[10];
    const float* conv1_w = (const float*)d_in[11];
    const float* conv1_b = (const float*)d_in[12];
    const float* conv33_w= (const float*)d_in[13];
    const float* conv33_b= (const float*)d_in[14];
    const float* conv55_w= (const float*)d_in[15];
    const float* conv55_b= (const float*)d_in[16];
    const float* conv4_w = (const float*)d_in[17];
    const float* conv4_b = (const float*)d_in[18];
    float* out = (float*)d_out;

    // LN1 stats + one-time tf32 weight split (fused)
    ln_stats<1><<<MTOT/8, 256>>>(x, q_w, kv_w, proj_w, conv1_w, conv4_w);        // 0
    gemm_mma<0><<<dim3(128, 6), 128>>>(x, nullptr,
                                       ln1_w, ln1_b, nullptr, nullptr);          // 1
    attn_kernel<<<dim3(8, 32, SPLITS), 128>>>();                                 // 2
    gemm_mma<1><<<dim3(128, 2), 128>>>(nullptr, proj_b,
                                       nullptr, nullptr, x, nullptr);            // 3 (profiled)
    ln_stats<2><<<MTOT/8, 256>>>(nullptr, nullptr, nullptr, nullptr,
                                 nullptr, nullptr);                              // 4
    gemm_mma<2><<<dim3(128, 4), 128>>>(nullptr, conv1_b,
                                       ln2_w, ln2_b, nullptr, nullptr);          // 5
    dw_gate_kernel<<<dim3(64, 4, 2), dim3(32, 8)>>>(conv33_w, conv33_b,
                                                    conv55_w, conv55_b);         // 6
    gemm_mma<3><<<dim3(128, 2), 128>>>(nullptr, conv4_b,
                                       nullptr, nullptr, nullptr, out);          // 7
}

// round 16
// speedup vs baseline: 1.3259x; 1.3259x over previous
#include <cuda_runtime.h>

#define BATCH 2
#define NSEQ 4096
#define CDIM 128
#define HEADS 4
#define HD 32
#define C2 256
#define MTOT (BATCH*NSEQ)
#define BH (BATCH*HEADS)
#define NROWS (BH*NSEQ)
#define SPLITS 4
#define TILES_PER_SPLIT (NSEQ/32/SPLITS)   // 32
#define KP 40
#define QSCALE (0.17677669529663687f * 1.4426950408889634f)

// pre-split weight table offsets (rows of 128)
#define WOFF_QKV   0            // [q(128); kv(256)]
#define WOFF_PROJ  49152
#define WOFF_CONV1 65536
#define WOFF_CONV4 98304
#define WTOTAL     114688

typedef unsigned long long u64;
typedef unsigned short u16;

// ---------------- scratch ----------------
__device__ float g_xmid [MTOT*CDIM];
__device__ float g_c1   [MTOT*C2];
__device__ float g_gate [MTOT*CDIM];
__device__ float g_pacc [SPLITS*NROWS*HD];
__device__ float g_pl   [SPLITS*NROWS];
__device__ float g_stats1[MTOT*2];
__device__ float g_stats2[MTOT*2];
__device__ float g_wh   [WTOTAL];    // tf32-rounded weights (hi)
__device__ float g_wl   [WTOTAL];    // tf32 residual (lo)
__device__ __align__(16) u16 g_qh[BH*NSEQ*HD];
__device__ __align__(16) u16 g_kh[BH*NSEQ*HD];
__device__ __align__(16) u16 g_vT[BH*NSEQ*HD];

// ---------------- helpers ----------------
__device__ __forceinline__ float ex2(float x) {
    float r; asm("ex2.approx.f32 %0, %1;" : "=f"(r) : "f"(x)); return r;
}
__device__ __forceinline__ unsigned cvt_tf32(float x) {
    unsigned r; asm("cvt.rna.tf32.f32 %0, %1;" : "=r"(r) : "f"(x)); return r;
}
__device__ __forceinline__ float tf32r(float x) { return __uint_as_float(cvt_tf32(x)); }
__device__ __forceinline__ unsigned bf16x2(float hi, float lo) {
    unsigned r;
    asm("cvt.rn.satfinite.bf16x2.f32 %0, %1, %2;" : "=r"(r) : "f"(hi), "f"(lo));
    return r;
}
__device__ __forceinline__ void mma_tf32(float* d,
    unsigned a0, unsigned a1, unsigned a2, unsigned a3, unsigned b0, unsigned b1) {
    asm("mma.sync.aligned.m16n8k8.row.col.f32.tf32.tf32.f32 "
        "{%0,%1,%2,%3}, {%4,%5,%6,%7}, {%8,%9}, {%0,%1,%2,%3};"
        : "+f"(d[0]), "+f"(d[1]), "+f"(d[2]), "+f"(d[3])
        : "r"(a0), "r"(a1), "r"(a2), "r"(a3), "r"(b0), "r"(b1));
}
__device__ __forceinline__ void mma_bf16(float* d,
    unsigned a0, unsigned a1, unsigned a2, unsigned a3, unsigned b0, unsigned b1) {
    asm("mma.sync.aligned.m16n8k16.row.col.f32.bf16.bf16.f32 "
        "{%0,%1,%2,%3}, {%4,%5,%6,%7}, {%8,%9}, {%0,%1,%2,%3};"
        : "+f"(d[0]), "+f"(d[1]), "+f"(d[2]), "+f"(d[3])
        : "r"(a0), "r"(a1), "r"(a2), "r"(a3), "r"(b0), "r"(b1));
}

// ---------------- LN stats (+ fused one-time weight split on WHICH==1) ----------------
template<int WHICH>
__global__ void __launch_bounds__(256) ln_stats(const float* __restrict__ xin,
                                                const float* __restrict__ q_w,
                                                const float* __restrict__ kv_w,
                                                const float* __restrict__ proj_w,
                                                const float* __restrict__ conv1_w,
                                                const float* __restrict__ conv4_w) {
    if (WHICH == 1) {
        const int wi = blockIdx.x*256 + threadIdx.x;
        if (wi < WTOTAL) {
            float v;
            if      (wi < 16384) v = q_w[wi];
            else if (wi < 49152) v = kv_w[wi - 16384];
            else if (wi < 65536) v = proj_w[wi - 49152];
            else if (wi < 98304) v = conv1_w[wi - 65536];
            else                 v = conv4_w[wi - 98304];
            float h = tf32r(v);
            g_wh[wi] = h;
            g_wl[wi] = tf32r(v - h);
        }
    }
    const float* in = (WHICH == 1) ? xin : g_xmid;
    float*       st = (WHICH == 1) ? g_stats1 : g_stats2;
    const int row = blockIdx.x*8 + (threadIdx.x >> 5);
    const int lane = threadIdx.x & 31;
    float4 v = *(const float4*)(in + (size_t)row*CDIM + lane*4);
    float s = (v.x + v.y) + (v.z + v.w);
    #pragma unroll
    for (int o = 16; o; o >>= 1) s += __shfl_xor_sync(0xffffffffu, s, o);
    const float mu = s * (1.0f/128.0f);
    float dx = v.x-mu, dy = v.y-mu, dz = v.z-mu, dw = v.w-mu;
    float q = (dx*dx + dy*dy) + (dz*dz + dw*dw);
    #pragma unroll
    for (int o = 16; o; o >>= 1) q += __shfl_xor_sync(0xffffffffu, q, o);
    if (lane == 0)
        *(float2*)&st[row*2] = make_float2(mu, rsqrtf(q*(1.0f/128.0f) + 1e-5f));
}

// ---------------- GEMM: tile m64 x o64, 4 warps, K=128 in 8 chunks; pre-split W ----------------
// MODE 0: A=x(arg)+LN1, single tf32, bf16 out (Q scale folded)
// MODE 1: A = split-KV reduce of g_pacc/g_pl (fused), 3xTF32, +bias +resid(x) -> g_xmid
//         2-stage register prefetch (grid-limited launch; double MLP).
// MODE 2: A=g_xmid+LN2, 3xTF32, +bias -> g_c1
// MODE 3: A=g_gate,     3xTF32, +bias +resid(g_xmid) -> out_ext
template<int MODE>
__global__ void __launch_bounds__(128) gemm_mma(const float* __restrict__ Aext,
                                                const float* __restrict__ bias,
                                                const float* __restrict__ lnw,
                                                const float* __restrict__ lnb,
                                                const float* __restrict__ resid_ext,
                                                float* __restrict__ out_ext) {
    constexpr bool EX = (MODE != 0);
    constexpr bool LN = (MODE == 0 || MODE == 2);
    constexpr int  PF = (MODE == 1) ? 2 : 1;      // prefetch depth
    constexpr int  WOFF = (MODE == 0) ? WOFF_QKV :
                          (MODE == 1) ? WOFF_PROJ :
                          (MODE == 2) ? WOFF_CONV1 : WOFF_CONV4;
    const float* A;
    if (MODE == 0)      A = Aext;
    else if (MODE == 1) A = nullptr;
    else if (MODE == 2) A = g_xmid;
    else                A = g_gate;
    const float* stats = (MODE == 0) ? g_stats1 : g_stats2;

    __shared__ float Ah[64][20], Wh[64][20];
    __shared__ float Al[EX ? 64 : 1][20], Wl[EX ? 64 : 1][20];

    const int t = threadIdx.x;
    const int warp = t >> 5, lane = t & 31;
    const int g = lane >> 2, tg = lane & 3;
    const int m0 = blockIdx.x * 64;
    const int o0 = blockIdx.y * 64;
    const int lrow = t >> 2, c4 = (t & 3) * 4;

    float s[8][4] = {};

    float2 st0, st1;
    if (LN) {
        st0 = *(const float2*)(stats + (size_t)(m0 + lrow)*2);
        st1 = *(const float2*)(stats + (size_t)(m0 + lrow + 32)*2);
    }

    // MODE 1: per-row per-head 1/l
    int b0_ = 0, n0_ = 0, b1_ = 0, n1_ = 0;
    float invl0[4], invl1[4];
    float4 p0[PF][SPLITS], p1[PF][SPLITS];
    if (MODE == 1) {
        int m_ = m0 + lrow;  b0_ = m_ >> 12;  n0_ = m_ & 4095;
        int m2_ = m_ + 32;   b1_ = m2_ >> 12; n1_ = m2_ & 4095;
        #pragma unroll
        for (int h = 0; h < 4; ++h) {
            size_t r0 = (size_t)((b0_*4 + h)*4096 + n0_);
            size_t r1 = (size_t)((b1_*4 + h)*4096 + n1_);
            float l0 = g_pl[r0] + g_pl[(size_t)NROWS + r0]
                     + g_pl[2*(size_t)NROWS + r0] + g_pl[3*(size_t)NROWS + r0];
            float l1 = g_pl[r1] + g_pl[(size_t)NROWS + r1]
                     + g_pl[2*(size_t)NROWS + r1] + g_pl[3*(size_t)NROWS + r1];
            invl0[h] = 1.0f / l0;
            invl1[h] = 1.0f / l1;
        }
    }

    float4 a0s[PF], a1s[PF], w0h[PF], w1h[PF], w0l[PF], w1l[PF], lw[PF], lb[PF];

#define GEMM_LOAD(kc_, sb_) {                                                   \
        const int k0_ = (kc_)*16;                                               \
        if (MODE == 1) {                                                        \
            const int h_ = k0_ >> 5;                                            \
            const int hb_ = (k0_ & 31) + c4;                                    \
            const size_t r0_ = (size_t)((b0_*4 + h_)*4096 + n0_);               \
            const size_t r1_ = (size_t)((b1_*4 + h_)*4096 + n1_);               \
            _Pragma("unroll")                                                   \
            for (int s_ = 0; s_ < SPLITS; ++s_) {                               \
                p0[sb_][s_] = *(const float4*)(g_pacc + (((size_t)s_*NROWS + r0_)<<5) + hb_); \
                p1[sb_][s_] = *(const float4*)(g_pacc + (((size_t)s_*NROWS + r1_)<<5) + hb_); \
            }                                                                   \
        } else {                                                                \
            a0s[sb_] = *(const float4*)(A + (size_t)(m0 + lrow     )*CDIM + k0_ + c4);\
            a1s[sb_] = *(const float4*)(A + (size_t)(m0 + lrow + 32)*CDIM + k0_ + c4);\
        }                                                                       \
        w0h[sb_] = *(const float4*)(g_wh + WOFF + (size_t)(o0 + lrow     )*CDIM + k0_ + c4); \
        w1h[sb_] = *(const float4*)(g_wh + WOFF + (size_t)(o0 + lrow + 32)*CDIM + k0_ + c4); \
        if (EX) {                                                               \
            w0l[sb_] = *(const float4*)(g_wl + WOFF + (size_t)(o0 + lrow     )*CDIM + k0_ + c4); \
            w1l[sb_] = *(const float4*)(g_wl + WOFF + (size_t)(o0 + lrow + 32)*CDIM + k0_ + c4); \
        }                                                                       \
        if (LN) { lw[sb_] = *(const float4*)(lnw + k0_ + c4);                   \
                  lb[sb_] = *(const float4*)(lnb + k0_ + c4); } }

    GEMM_LOAD(0, 0);
    if (PF == 2) GEMM_LOAD(1, 1);

    #pragma unroll
    for (int kc = 0; kc < 8; ++kc) {
        const int sb = (PF == 2) ? (kc & 1) : 0;
        if (kc) __syncthreads();

        float4 a0, a1;
        if (MODE == 1) {
            const int h_ = kc >> 1;
            float4* q0 = p0[sb];
            float4* q1 = p1[sb];
            a0 = make_float4((q0[0].x+q0[1].x+q0[2].x+q0[3].x)*invl0[h_],
                             (q0[0].y+q0[1].y+q0[2].y+q0[3].y)*invl0[h_],
                             (q0[0].z+q0[1].z+q0[2].z+q0[3].z)*invl0[h_],
                             (q0[0].w+q0[1].w+q0[2].w+q0[3].w)*invl0[h_]);
            a1 = make_float4((q1[0].x+q1[1].x+q1[2].x+q1[3].x)*invl1[h_],
                             (q1[0].y+q1[1].y+q1[2].y+q1[3].y)*invl1[h_],
                             (q1[0].z+q1[1].z+q1[2].z+q1[3].z)*invl1[h_],
                             (q1[0].w+q1[1].w+q1[2].w+q1[3].w)*invl1[h_]);
        } else {
            a0 = a0s[sb];
            a1 = a1s[sb];
        }
        if (LN) {
            a0.x = (a0.x - st0.x)*st0.y*lw[sb].x + lb[sb].x;
            a0.y = (a0.y - st0.x)*st0.y*lw[sb].y + lb[sb].y;
            a0.z = (a0.z - st0.x)*st0.y*lw[sb].z + lb[sb].z;
            a0.w = (a0.w - st0.x)*st0.y*lw[sb].w + lb[sb].w;
            a1.x = (a1.x - st1.x)*st1.y*lw[sb].x + lb[sb].x;
            a1.y = (a1.y - st1.x)*st1.y*lw[sb].y + lb[sb].y;
            a1.z = (a1.z - st1.x)*st1.y*lw[sb].z + lb[sb].z;
            a1.w = (a1.w - st1.x)*st1.y*lw[sb].w + lb[sb].w;
        }
        {
            float4 h0, h1;
            h0.x = tf32r(a0.x); h0.y = tf32r(a0.y); h0.z = tf32r(a0.z); h0.w = tf32r(a0.w);
            h1.x = tf32r(a1.x); h1.y = tf32r(a1.y); h1.z = tf32r(a1.z); h1.w = tf32r(a1.w);
            *(float4*)&Ah[lrow     ][c4] = h0;
            *(float4*)&Ah[lrow + 32][c4] = h1;
            if (EX) {
                float4 l0, l1;
                l0.x = tf32r(a0.x - h0.x); l0.y = tf32r(a0.y - h0.y);
                l0.z = tf32r(a0.z - h0.z); l0.w = tf32r(a0.w - h0.w);
                l1.x = tf32r(a1.x - h1.x); l1.y = tf32r(a1.y - h1.y);
                l1.z = tf32r(a1.z - h1.z); l1.w = tf32r(a1.w - h1.w);
                *(float4*)&Al[lrow     ][c4] = l0;
                *(float4*)&Al[lrow + 32][c4] = l1;
            }
            *(float4*)&Wh[lrow     ][c4] = w0h[sb];
            *(float4*)&Wh[lrow + 32][c4] = w1h[sb];
            if (EX) {
                *(float4*)&Wl[lrow     ][c4] = w0l[sb];
                *(float4*)&Wl[lrow + 32][c4] = w1l[sb];
            }
        }
        __syncthreads();
        if (PF == 2) {
            if (kc + 2 < 8) GEMM_LOAD(kc + 2, sb);
        } else {
            if (kc + 1 < 8) GEMM_LOAD(kc + 1, 0);
        }

        #pragma unroll
        for (int ks = 0; ks < 2; ++ks) {
            const int k = ks * 8;
            const int mr = 16*warp;
            unsigned ah[4], al[4];
            ah[0] = __float_as_uint(Ah[mr + g    ][k + tg    ]);
            ah[1] = __float_as_uint(Ah[mr + g + 8][k + tg    ]);
            ah[2] = __float_as_uint(Ah[mr + g    ][k + tg + 4]);
            ah[3] = __float_as_uint(Ah[mr + g + 8][k + tg + 4]);
            if (EX) {
                al[0] = __float_as_uint(Al[mr + g    ][k + tg    ]);
                al[1] = __float_as_uint(Al[mr + g + 8][k + tg    ]);
                al[2] = __float_as_uint(Al[mr + g    ][k + tg + 4]);
                al[3] = __float_as_uint(Al[mr + g + 8][k + tg + 4]);
            }
            #pragma unroll
            for (int nt = 0; nt < 8; ++nt) {
                unsigned bh0 = __float_as_uint(Wh[8*nt + g][k + tg    ]);
                unsigned bh1 = __float_as_uint(Wh[8*nt + g][k + tg + 4]);
                mma_tf32(s[nt], ah[0], ah[1], ah[2], ah[3], bh0, bh1);
                if (EX) {
                    unsigned bl0 = __float_as_uint(Wl[8*nt + g][k + tg    ]);
                    unsigned bl1 = __float_as_uint(Wl[8*nt + g][k + tg + 4]);
                    mma_tf32(s[nt], ah[0], ah[1], ah[2], ah[3], bl0, bl1);
                    mma_tf32(s[nt], al[0], al[1], al[2], al[3], bh0, bh1);
                }
            }
        }
    }
#undef GEMM_LOAD

    // ---- epilogue ----
    const int mA = m0 + 16*warp + g;
    #pragma unroll
    for (int nt = 0; nt < 8; ++nt) {
        const int o = o0 + 8*nt + 2*tg;
        float2 v01 = make_float2(s[nt][0], s[nt][1]);
        float2 v23 = make_float2(s[nt][2], s[nt][3]);
        if (MODE == 0) {
            #pragma unroll
            for (int hf = 0; hf < 2; ++hf) {
                const int m = mA + 8*hf;
                float2 v = hf ? v23 : v01;
                const int b = m >> 12, n = m & 4095;
                if (o < 128) {
                    const int head = o >> 5, hd = o & 31;
                    *(unsigned*)&g_qh[((size_t)(b*HEADS + head)*NSEQ + n)*HD + hd] =
                        bf16x2(v.y*QSCALE, v.x*QSCALE);
                } else if (o < 256) {
                    const int oo = o - 128, head = oo >> 5, hd = oo & 31;
                    *(unsigned*)&g_kh[((size_t)(b*HEADS + head)*NSEQ + n)*HD + hd] =
                        bf16x2(v.y, v.x);
                } else {
                    const int oo = o - 256, head = oo >> 5, hd = oo & 31;
                    unsigned u = bf16x2(v.y, v.x);
                    size_t base = ((size_t)((b*HEADS + head)*128 + (n >> 5))*32 + hd)*32 + (n & 31);
                    g_vT[base]      = (u16)(u & 0xffffu);
                    g_vT[base + 32] = (u16)(u >> 16);
                }
            }
        } else if (MODE == 2) {
            float2 bv = *(const float2*)(bias + o);
            *(float2*)&g_c1[(size_t)mA*C2 + o] =
                make_float2(v01.x + bv.x, v01.y + bv.y);
            *(float2*)&g_c1[(size_t)(mA+8)*C2 + o] =
                make_float2(v23.x + bv.x, v23.y + bv.y);
        } else {
            const float* rs = (MODE == 1) ? resid_ext : g_xmid;
            float*       ds = (MODE == 1) ? g_xmid    : out_ext;
            float2 bv = *(const float2*)(bias + o);
            float2 r0 = *(const float2*)(rs + (size_t)mA*CDIM + o);
            float2 r1 = *(const float2*)(rs + (size_t)(mA+8)*CDIM + o);
            *(float2*)&ds[(size_t)mA*CDIM + o] =
                make_float2(v01.x + bv.x + r0.x, v01.y + bv.y + r0.y);
            *(float2*)&ds[(size_t)(mA+8)*CDIM + o] =
                make_float2(v23.x + bv.x + r1.x, v23.y + bv.y + r1.y);
        }
    }
}

// ---------------- Flash attention: bf16 m16n8k16, split-KV=4 (champion version) ----------------
__global__ void __launch_bounds__(128, 4) attn_kernel() {
    const int bh    = blockIdx.x;
    const int split = blockIdx.z;
    const int t     = threadIdx.x;
    const int warp  = t >> 5;
    const int lane  = t & 31;
    const int g     = lane >> 2;
    const int tg    = lane & 3;

    const int q0 = blockIdx.y*128 + warp*32;
    const u16* Qb  = g_qh + ((size_t)bh*NSEQ + q0)*HD;
    const u16* Kb  = g_kh + ((size_t)bh*NSEQ + (size_t)split*(NSEQ/SPLITS))*HD;
    const u16* Vtb = g_vT + ((size_t)(bh*128 + split*TILES_PER_SPLIT))*1024;

    unsigned qf[2][2][4];
    #pragma unroll
    for (int mt = 0; mt < 2; ++mt)
        #pragma unroll
        for (int kk = 0; kk < 2; ++kk) {
            qf[mt][kk][0] = *(const unsigned*)&Qb[(16*mt + g    )*HD + 16*kk + 2*tg    ];
            qf[mt][kk][1] = *(const unsigned*)&Qb[(16*mt + g + 8)*HD + 16*kk + 2*tg    ];
            qf[mt][kk][2] = *(const unsigned*)&Qb[(16*mt + g    )*HD + 16*kk + 2*tg + 8];
            qf[mt][kk][3] = *(const unsigned*)&Qb[(16*mt + g + 8)*HD + 16*kk + 2*tg + 8];
        }

    __shared__ u16 Ks[2][32][KP];
    __shared__ u16 Vt[2][32][KP];

    float o[2][4][4] = {};
    float l[4] = {};

    const int lr  = t >> 2;
    const int lc8 = (t & 3) * 8;
    const float4* kptr = (const float4*)Kb  + t;
    const float4* vptr = (const float4*)Vtb + t;

    float4 ka = kptr[0];
    float4 va = vptr[0];

    for (int kt = 0; kt < TILES_PER_SPLIT; ++kt) {
        const int buf = kt & 1;
        *(float4*)&Ks[buf][lr][lc8] = ka;
        *(float4*)&Vt[buf][lr][lc8] = va;
        __syncthreads();

        if (kt + 1 < TILES_PER_SPLIT) {
            ka = kptr[(kt+1)*128];
            va = vptr[(kt+1)*128];
        }

        float s[2][4][4] = {};
        #pragma unroll
        for (int nt = 0; nt < 4; ++nt) {
            #pragma unroll
            for (int kk = 0; kk < 2; ++kk) {
                unsigned b0 = *(const unsigned*)&Ks[buf][8*nt + g][16*kk + 2*tg    ];
                unsigned b1 = *(const unsigned*)&Ks[buf][8*nt + g][16*kk + 2*tg + 8];
                mma_bf16(s[0][nt], qf[0][kk][0], qf[0][kk][1], qf[0][kk][2], qf[0][kk][3], b0, b1);
                mma_bf16(s[1][nt], qf[1][kk][0], qf[1][kk][1], qf[1][kk][2], qf[1][kk][3], b0, b1);
            }
        }

        unsigned pk[2][4][2];
        #pragma unroll
        for (int nt = 0; nt < 4; ++nt)
            #pragma unroll
            for (int mt = 0; mt < 2; ++mt) {
                float e0 = ex2(s[mt][nt][0]);
                float e1 = ex2(s[mt][nt][1]);
                float e2 = ex2(s[mt][nt][2]);
                float e3 = ex2(s[mt][nt][3]);
                l[2*mt]   += e0 + e1;
                l[2*mt+1] += e2 + e3;
                pk[mt][nt][0] = bf16x2(e1, e0);
                pk[mt][nt][1] = bf16x2(e3, e2);
            }

        #pragma unroll
        for (int kk2 = 0; kk2 < 2; ++kk2) {
            #pragma unroll
            for (int nd = 0; nd < 4; ++nd) {
                unsigned b0 = *(const unsigned*)&Vt[buf][8*nd + g][16*kk2 + 2*tg    ];
                unsigned b1 = *(const unsigned*)&Vt[buf][8*nd + g][16*kk2 + 2*tg + 8];
                #pragma unroll
                for (int mt = 0; mt < 2; ++mt)
                    mma_bf16(o[mt][nd],
                             pk[mt][2*kk2][0], pk[mt][2*kk2][1],
                             pk[mt][2*kk2+1][0], pk[mt][2*kk2+1][1],
                             b0, b1);
            }
        }
    }

    #pragma unroll
    for (int i = 0; i < 4; ++i) {
        l[i] += __shfl_xor_sync(0xffffffffu, l[i], 1);
        l[i] += __shfl_xor_sync(0xffffffffu, l[i], 2);
    }

    #pragma unroll
    for (int mt = 0; mt < 2; ++mt) {
        const size_t row = (size_t)bh*NSEQ + q0 + 16*mt + g;
        float* base0 = g_pacc + ((size_t)split*NROWS + row)*HD;
        float* base1 = base0 + 8*HD;
        #pragma unroll
        for (int nd = 0; nd < 4; ++nd) {
            *(float2*)(base0 + 8*nd + 2*tg) = make_float2(o[mt][nd][0], o[mt][nd][1]);
            *(float2*)(base1 + 8*nd + 2*tg) = make_float2(o[mt][nd][2], o[mt][nd][3]);
        }
        if (tg == 0) {
            g_pl[(size_t)split*NROWS + row    ] = l[2*mt];
            g_pl[(size_t)split*NROWS + row + 8] = l[2*mt+1];
        }
    }
}

// ---------------- dw 3x3 + 5x5 + gate: spatially tiled, smem halo ----------------
__global__ void __launch_bounds__(256) dw_gate_kernel(const float* __restrict__ w33,
                                                      const float* __restrict__ b33,
                                                      const float* __restrict__ w55,
                                                      const float* __restrict__ b55) {
    __shared__ float sIn[144][64];
    __shared__ float sw3[64][9];
    __shared__ float sw5[64][25];
    __shared__ float sbb[64];

    const int c   = threadIdx.x;
    const int py  = threadIdx.y;
    const int tid = py*32 + c;
    const int ca0 = blockIdx.y * 32;
    const int bz  = blockIdx.z;
    const int ty0 = (blockIdx.x >> 3) * 8;
    const int tx0 = (blockIdx.x & 7) * 8;

    for (int i = tid; i < 64*9; i += 256) {
        int s = i / 9, k = i - s*9;
        int gc = (s < 32) ? (ca0 + s) : (128 + ca0 + s - 32);
        sw3[s][k] = w33[gc*9 + k];
    }
    for (int i = tid; i < 64*25; i += 256) {
        int s = i / 25, k = i - s*25;
        int gc = (s < 32) ? (ca0 + s) : (128 + ca0 + s - 32);
        sw5[s][k] = w55[gc*25 + k];
    }
    if (tid < 64) {
        int gc = (tid < 32) ? (ca0 + tid) : (128 + ca0 + tid - 32);
        sbb[tid] = b33[gc] + b55[gc];
    }

    const float* cbase = g_c1 + (size_t)bz*NSEQ*C2;
    for (int i = tid; i < 2304; i += 256) {
        int px = i >> 4, c4 = i & 15;
        int hy = ty0 + (px/12) - 2, hx = tx0 + (px - (px/12)*12) - 2;
        float4 v = make_float4(0.f, 0.f, 0.f, 0.f);
        if (hy >= 0 && hy < 64 && hx >= 0 && hx < 64) {
            int gc = (c4 < 8) ? (ca0 + c4*4) : (128 + ca0 + (c4-8)*4);
            v = *(const float4*)(cbase + (size_t)(hy*64 + hx)*C2 + gc);
        }
        *(float4*)&sIn[px][c4*4] = v;
    }
    __syncthreads();

    float w5a[25], w5g[25];
    #pragma unroll
    for (int k = 0; k < 25; ++k) { w5a[k] = sw5[c][k]; w5g[k] = sw5[32+c][k]; }
    float w3a[9], w3g[9];
    #pragma unroll
    for (int k = 0; k < 9; ++k)  { w3a[k] = sw3[c][k]; w3g[k] = sw3[32+c][k]; }
    const float ba = sbb[c], bg = sbb[32+c];

    float* gout = g_gate + ((size_t)bz*NSEQ + (ty0+py)*64 + tx0)*CDIM + ca0 + c;

    #pragma unroll
    for (int x = 0; x < 8; ++x) {
        const int p0 = (py+2)*12 + (x+2);
        float a = ba + sIn[p0][c];
        float g = bg + sIn[p0][32+c];
        #pragma unroll
        for (int dy = -2; dy <= 2; ++dy) {
            #pragma unroll
            for (int dx = -2; dx <= 2; ++dx) {
                const int pp = p0 + dy*12 + dx;
                const float va = sIn[pp][c];
                const float vg = sIn[pp][32+c];
                const int i5 = (dy+2)*5 + (dx+2);
                a = fmaf(va, w5a[i5], a);
                g = fmaf(vg, w5g[i5], g);
                if (dy >= -1 && dy <= 1 && dx >= -1 && dx <= 1) {
                    const int i3 = (dy+1)*3 + (dx+1);
                    a = fmaf(va, w3a[i3], a);
                    g = fmaf(vg, w3g[i3], g);
                }
            }
        }
        gout[x*CDIM] = a * g;
    }
}

// ---------------- launch ----------------
extern "C" void kernel_launch(void* const* d_in, const int* in_sizes, int n_in,
                              void* d_out, int out_size) {
    (void)in_sizes; (void)n_in; (void)out_size;
    const float* x       = (const float*)d_in[0];
    const float* ln1_w   = (const float*)d_in[3];
    const float* ln1_b   = (const float*)d_in[4];
    const float* q_w     = (const float*)d_in[5];
    const float* kv_w    = (const float*)d_in[6];
    const float* proj_w  = (const float*)d_in[7];
    const float* proj_b  = (const float*)d_in[8];
    const float* ln2_w   = (const float*)d_in[9];
    const float* ln2_b   = (const float*)d_in[10];
    const float* conv1_w = (const float*)d_in[11];
    const float* conv1_b = (const float*)d_in[12];
    const float* conv33_w= (const float*)d_in[13];
    const float* conv33_b= (const float*)d_in[14];
    const float* conv55_w= (const float*)d_in[15];
    const float* conv55_b= (const float*)d_in[16];
    const float* conv4_w = (const float*)d_in[17];
    const float* conv4_b = (const float*)d_in[18];
    float* out = (float*)d_out;

    // LN1 stats + one-time tf32 weight split (fused)
    ln_stats<1><<<MTOT/8, 256>>>(x, q_w, kv_w, proj_w, conv1_w, conv4_w);        // 0
    gemm_mma<0><<<dim3(128, 6), 128>>>(x, nullptr,
                                       ln1_w, ln1_b, nullptr, nullptr);          // 1
    attn_kernel<<<dim3(8, 32, SPLITS), 128>>>();                                 // 2
    gemm_mma<1><<<dim3(128, 2), 128>>>(nullptr, proj_b,
                                       nullptr, nullptr, x, nullptr);            // 3 (profiled)
    ln_stats<2><<<MTOT/8, 256>>>(nullptr, nullptr, nullptr, nullptr,
                                 nullptr, nullptr);                              // 4
    gemm_mma<2><<<dim3(128, 4), 128>>>(nullptr, conv1_b,
                                       ln2_w, ln2_b, nullptr, nullptr);          // 5
    dw_gate_kernel<<<dim3(64, 4, 2), dim3(32, 8)>>>(conv33_w, conv33_b,
                                                    conv55_w, conv55_b);         // 6
    gemm_mma<3><<<dim3(128, 2), 128>>>(nullptr, conv4_b,
                                       nullptr, nullptr, nullptr, out);          // 7
}

// round 17
// speedup vs baseline: 1.3466x; 1.0156x over previous
#include <cuda_runtime.h>

#define BATCH 2
#define NSEQ 4096
#define CDIM 128
#define HEADS 4
#define HD 32
#define C2 256
#define MTOT (BATCH*NSEQ)
#define BH (BATCH*HEADS)
#define NROWS (BH*NSEQ)
#define SPLITS 4
#define TILES_PER_SPLIT (NSEQ/32/SPLITS)   // 32
#define KP 40
#define QSCALE (0.17677669529663687f * 1.4426950408889634f)

// pre-split weight table offsets (rows of 128)
#define WOFF_QKV   0            // [q(128); kv(256)]
#define WOFF_PROJ  49152
#define WOFF_CONV1 65536
#define WOFF_CONV4 98304
#define WTOTAL     114688

typedef unsigned long long u64;
typedef unsigned short u16;

// ---------------- scratch ----------------
__device__ float g_xmid [MTOT*CDIM];
__device__ float g_c1   [MTOT*C2];
__device__ float g_gate [MTOT*CDIM];
__device__ __align__(16) u16 g_pacc[SPLITS*NROWS*HD];   // bf16 partial PV sums
__device__ float g_pl   [SPLITS*NROWS];
__device__ float g_stats1[MTOT*2];
__device__ float g_stats2[MTOT*2];
__device__ float g_wh   [WTOTAL];    // tf32-rounded weights (hi)
__device__ float g_wl   [WTOTAL];    // tf32 residual (lo)
__device__ __align__(16) u16 g_qh[BH*NSEQ*HD];
__device__ __align__(16) u16 g_kh[BH*NSEQ*HD];
__device__ __align__(16) u16 g_vT[BH*NSEQ*HD];

// ---------------- helpers ----------------
__device__ __forceinline__ float ex2(float x) {
    float r; asm("ex2.approx.f32 %0, %1;" : "=f"(r) : "f"(x)); return r;
}
__device__ __forceinline__ unsigned cvt_tf32(float x) {
    unsigned r; asm("cvt.rna.tf32.f32 %0, %1;" : "=r"(r) : "f"(x)); return r;
}
__device__ __forceinline__ float tf32r(float x) { return __uint_as_float(cvt_tf32(x)); }
__device__ __forceinline__ unsigned bf16x2(float hi, float lo) {
    unsigned r;
    asm("cvt.rn.satfinite.bf16x2.f32 %0, %1, %2;" : "=r"(r) : "f"(hi), "f"(lo));
    return r;
}
__device__ __forceinline__ float bf_lo(unsigned u) { return __uint_as_float(u << 16); }
__device__ __forceinline__ float bf_hi(unsigned u) { return __uint_as_float(u & 0xffff0000u); }
__device__ __forceinline__ void mma_tf32(float* d,
    unsigned a0, unsigned a1, unsigned a2, unsigned a3, unsigned b0, unsigned b1) {
    asm("mma.sync.aligned.m16n8k8.row.col.f32.tf32.tf32.f32 "
        "{%0,%1,%2,%3}, {%4,%5,%6,%7}, {%8,%9}, {%0,%1,%2,%3};"
        : "+f"(d[0]), "+f"(d[1]), "+f"(d[2]), "+f"(d[3])
        : "r"(a0), "r"(a1), "r"(a2), "r"(a3), "r"(b0), "r"(b1));
}
__device__ __forceinline__ void mma_bf16(float* d,
    unsigned a0, unsigned a1, unsigned a2, unsigned a3, unsigned b0, unsigned b1) {
    asm("mma.sync.aligned.m16n8k16.row.col.f32.bf16.bf16.f32 "
        "{%0,%1,%2,%3}, {%4,%5,%6,%7}, {%8,%9}, {%0,%1,%2,%3};"
        : "+f"(d[0]), "+f"(d[1]), "+f"(d[2]), "+f"(d[3])
        : "r"(a0), "r"(a1), "r"(a2), "r"(a3), "r"(b0), "r"(b1));
}

// ---------------- LN stats (+ fused one-time weight split on WHICH==1) ----------------
template<int WHICH>
__global__ void __launch_bounds__(256) ln_stats(const float* __restrict__ xin,
                                                const float* __restrict__ q_w,
                                                const float* __restrict__ kv_w,
                                                const float* __restrict__ proj_w,
                                                const float* __restrict__ conv1_w,
                                                const float* __restrict__ conv4_w) {
    if (WHICH == 1) {
        const int wi = blockIdx.x*256 + threadIdx.x;
        if (wi < WTOTAL) {
            float v;
            if      (wi < 16384) v = q_w[wi];
            else if (wi < 49152) v = kv_w[wi - 16384];
            else if (wi < 65536) v = proj_w[wi - 49152];
            else if (wi < 98304) v = conv1_w[wi - 65536];
            else                 v = conv4_w[wi - 98304];
            float h = tf32r(v);
            g_wh[wi] = h;
            g_wl[wi] = tf32r(v - h);
        }
    }
    const float* in = (WHICH == 1) ? xin : g_xmid;
    float*       st = (WHICH == 1) ? g_stats1 : g_stats2;
    const int row = blockIdx.x*8 + (threadIdx.x >> 5);
    const int lane = threadIdx.x & 31;
    float4 v = *(const float4*)(in + (size_t)row*CDIM + lane*4);
    float s = (v.x + v.y) + (v.z + v.w);
    #pragma unroll
    for (int o = 16; o; o >>= 1) s += __shfl_xor_sync(0xffffffffu, s, o);
    const float mu = s * (1.0f/128.0f);
    float dx = v.x-mu, dy = v.y-mu, dz = v.z-mu, dw = v.w-mu;
    float q = (dx*dx + dy*dy) + (dz*dz + dw*dw);
    #pragma unroll
    for (int o = 16; o; o >>= 1) q += __shfl_xor_sync(0xffffffffu, q, o);
    if (lane == 0)
        *(float2*)&st[row*2] = make_float2(mu, rsqrtf(q*(1.0f/128.0f) + 1e-5f));
}

// ---------------- GEMM: tile m64 x o64, 4 warps, K=128 in 8 chunks; pre-split W ----------------
// MODE 0: A=x(arg)+LN1, single tf32, bf16 out (Q scale folded)
// MODE 1: A = split-KV reduce of bf16 g_pacc / fp32 g_pl (fused), 3xTF32,
//         +bias +resid(x) -> g_xmid.  2-stage register prefetch.
// MODE 2: A=g_xmid+LN2, 3xTF32, +bias -> g_c1
// MODE 3: A=g_gate,     3xTF32, +bias +resid(g_xmid) -> out_ext
template<int MODE>
__global__ void __launch_bounds__(128) gemm_mma(const float* __restrict__ Aext,
                                                const float* __restrict__ bias,
                                                const float* __restrict__ lnw,
                                                const float* __restrict__ lnb,
                                                const float* __restrict__ resid_ext,
                                                float* __restrict__ out_ext) {
    constexpr bool EX = (MODE != 0);
    constexpr bool LN = (MODE == 0 || MODE == 2);
    constexpr int  PF = (MODE == 1) ? 2 : 1;
    constexpr int  WOFF = (MODE == 0) ? WOFF_QKV :
                          (MODE == 1) ? WOFF_PROJ :
                          (MODE == 2) ? WOFF_CONV1 : WOFF_CONV4;
    const float* A;
    if (MODE == 0)      A = Aext;
    else if (MODE == 1) A = nullptr;
    else if (MODE == 2) A = g_xmid;
    else                A = g_gate;
    const float* stats = (MODE == 0) ? g_stats1 : g_stats2;

    __shared__ float Ah[64][20], Wh[64][20];
    __shared__ float Al[EX ? 64 : 1][20], Wl[EX ? 64 : 1][20];

    const int t = threadIdx.x;
    const int warp = t >> 5, lane = t & 31;
    const int g = lane >> 2, tg = lane & 3;
    const int m0 = blockIdx.x * 64;
    const int o0 = blockIdx.y * 64;
    const int lrow = t >> 2, c4 = (t & 3) * 4;

    float s[8][4] = {};

    float2 st0, st1;
    if (LN) {
        st0 = *(const float2*)(stats + (size_t)(m0 + lrow)*2);
        st1 = *(const float2*)(stats + (size_t)(m0 + lrow + 32)*2);
    }

    // MODE 1: per-row per-head 1/l
    int b0_ = 0, n0_ = 0, b1_ = 0, n1_ = 0;
    float invl0[4], invl1[4];
    uint2 p0[PF][SPLITS], p1[PF][SPLITS];
    if (MODE == 1) {
        int m_ = m0 + lrow;  b0_ = m_ >> 12;  n0_ = m_ & 4095;
        int m2_ = m_ + 32;   b1_ = m2_ >> 12; n1_ = m2_ & 4095;
        #pragma unroll
        for (int h = 0; h < 4; ++h) {
            size_t r0 = (size_t)((b0_*4 + h)*4096 + n0_);
            size_t r1 = (size_t)((b1_*4 + h)*4096 + n1_);
            float l0 = g_pl[r0] + g_pl[(size_t)NROWS + r0]
                     + g_pl[2*(size_t)NROWS + r0] + g_pl[3*(size_t)NROWS + r0];
            float l1 = g_pl[r1] + g_pl[(size_t)NROWS + r1]
                     + g_pl[2*(size_t)NROWS + r1] + g_pl[3*(size_t)NROWS + r1];
            invl0[h] = 1.0f / l0;
            invl1[h] = 1.0f / l1;
        }
    }

    float4 a0s[PF], a1s[PF], w0h[PF], w1h[PF], w0l[PF], w1l[PF], lw[PF], lb[PF];

#define GEMM_LOAD(kc_, sb_) {                                                   \
        const int k0_ = (kc_)*16;                                               \
        if (MODE == 1) {                                                        \
            const int h_ = k0_ >> 5;                                            \
            const int hb_ = (k0_ & 31) + c4;                                    \
            const size_t r0_ = (size_t)((b0_*4 + h_)*4096 + n0_);               \
            const size_t r1_ = (size_t)((b1_*4 + h_)*4096 + n1_);               \
            _Pragma("unroll")                                                   \
            for (int s_ = 0; s_ < SPLITS; ++s_) {                               \
                p0[sb_][s_] = *(const uint2*)(g_pacc + (((size_t)s_*NROWS + r0_)<<5) + hb_); \
                p1[sb_][s_] = *(const uint2*)(g_pacc + (((size_t)s_*NROWS + r1_)<<5) + hb_); \
            }                                                                   \
        } else {                                                                \
            a0s[sb_] = *(const float4*)(A + (size_t)(m0 + lrow     )*CDIM + k0_ + c4);\
            a1s[sb_] = *(const float4*)(A + (size_t)(m0 + lrow + 32)*CDIM + k0_ + c4);\
        }                                                                       \
        w0h[sb_] = *(const float4*)(g_wh + WOFF + (size_t)(o0 + lrow     )*CDIM + k0_ + c4); \
        w1h[sb_] = *(const float4*)(g_wh + WOFF + (size_t)(o0 + lrow + 32)*CDIM + k0_ + c4); \
        if (EX) {                                                               \
            w0l[sb_] = *(const float4*)(g_wl + WOFF + (size_t)(o0 + lrow     )*CDIM + k0_ + c4); \
            w1l[sb_] = *(const float4*)(g_wl + WOFF + (size_t)(o0 + lrow + 32)*CDIM + k0_ + c4); \
        }                                                                       \
        if (LN) { lw[sb_] = *(const float4*)(lnw + k0_ + c4);                   \
                  lb[sb_] = *(const float4*)(lnb + k0_ + c4); } }

    GEMM_LOAD(0, 0);
    if (PF == 2) GEMM_LOAD(1, 1);

    #pragma unroll
    for (int kc = 0; kc < 8; ++kc) {
        const int sb = (PF == 2) ? (kc & 1) : 0;
        if (kc) __syncthreads();

        float4 a0, a1;
        if (MODE == 1) {
            const int h_ = kc >> 1;
            float ax = 0.f, ay = 0.f, az = 0.f, aw = 0.f;
            float bx = 0.f, by = 0.f, bz = 0.f, bw = 0.f;
            #pragma unroll
            for (int s_ = 0; s_ < SPLITS; ++s_) {
                uint2 u0 = p0[sb][s_];
                uint2 u1 = p1[sb][s_];
                ax += bf_lo(u0.x); ay += bf_hi(u0.x);
                az += bf_lo(u0.y); aw += bf_hi(u0.y);
                bx += bf_lo(u1.x); by += bf_hi(u1.x);
                bz += bf_lo(u1.y); bw += bf_hi(u1.y);
            }
            a0 = make_float4(ax*invl0[h_], ay*invl0[h_], az*invl0[h_], aw*invl0[h_]);
            a1 = make_float4(bx*invl1[h_], by*invl1[h_], bz*invl1[h_], bw*invl1[h_]);
        } else {
            a0 = a0s[sb];
            a1 = a1s[sb];
        }
        if (LN) {
            a0.x = (a0.x - st0.x)*st0.y*lw[sb].x + lb[sb].x;
            a0.y = (a0.y - st0.x)*st0.y*lw[sb].y + lb[sb].y;
            a0.z = (a0.z - st0.x)*st0.y*lw[sb].z + lb[sb].z;
            a0.w = (a0.w - st0.x)*st0.y*lw[sb].w + lb[sb].w;
            a1.x = (a1.x - st1.x)*st1.y*lw[sb].x + lb[sb].x;
            a1.y = (a1.y - st1.x)*st1.y*lw[sb].y + lb[sb].y;
            a1.z = (a1.z - st1.x)*st1.y*lw[sb].z + lb[sb].z;
            a1.w = (a1.w - st1.x)*st1.y*lw[sb].w + lb[sb].w;
        }
        {
            float4 h0, h1;
            h0.x = tf32r(a0.x); h0.y = tf32r(a0.y); h0.z = tf32r(a0.z); h0.w = tf32r(a0.w);
            h1.x = tf32r(a1.x); h1.y = tf32r(a1.y); h1.z = tf32r(a1.z); h1.w = tf32r(a1.w);
            *(float4*)&Ah[lrow     ][c4] = h0;
            *(float4*)&Ah[lrow + 32][c4] = h1;
            if (EX) {
                float4 l0, l1;
                l0.x = tf32r(a0.x - h0.x); l0.y = tf32r(a0.y - h0.y);
                l0.z = tf32r(a0.z - h0.z); l0.w = tf32r(a0.w - h0.w);
                l1.x = tf32r(a1.x - h1.x); l1.y = tf32r(a1.y - h1.y);
                l1.z = tf32r(a1.z - h1.z); l1.w = tf32r(a1.w - h1.w);
                *(float4*)&Al[lrow     ][c4] = l0;
                *(float4*)&Al[lrow + 32][c4] = l1;
            }
            *(float4*)&Wh[lrow     ][c4] = w0h[sb];
            *(float4*)&Wh[lrow + 32][c4] = w1h[sb];
            if (EX) {
                *(float4*)&Wl[lrow     ][c4] = w0l[sb];
                *(float4*)&Wl[lrow + 32][c4] = w1l[sb];
            }
        }
        __syncthreads();
        if (PF == 2) {
            if (kc + 2 < 8) GEMM_LOAD(kc + 2, sb);
        } else {
            if (kc + 1 < 8) GEMM_LOAD(kc + 1, 0);
        }

        #pragma unroll
        for (int ks = 0; ks < 2; ++ks) {
            const int k = ks * 8;
            const int mr = 16*warp;
            unsigned ah[4], al[4];
            ah[0] = __float_as_uint(Ah[mr + g    ][k + tg    ]);
            ah[1] = __float_as_uint(Ah[mr + g + 8][k + tg    ]);
            ah[2] = __float_as_uint(Ah[mr + g    ][k + tg + 4]);
            ah[3] = __float_as_uint(Ah[mr + g + 8][k + tg + 4]);
            if (EX) {
                al[0] = __float_as_uint(Al[mr + g    ][k + tg    ]);
                al[1] = __float_as_uint(Al[mr + g + 8][k + tg    ]);
                al[2] = __float_as_uint(Al[mr + g    ][k + tg + 4]);
                al[3] = __float_as_uint(Al[mr + g + 8][k + tg + 4]);
            }
            #pragma unroll
            for (int nt = 0; nt < 8; ++nt) {
                unsigned bh0 = __float_as_uint(Wh[8*nt + g][k + tg    ]);
                unsigned bh1 = __float_as_uint(Wh[8*nt + g][k + tg + 4]);
                mma_tf32(s[nt], ah[0], ah[1], ah[2], ah[3], bh0, bh1);
                if (EX) {
                    unsigned bl0 = __float_as_uint(Wl[8*nt + g][k + tg    ]);
                    unsigned bl1 = __float_as_uint(Wl[8*nt + g][k + tg + 4]);
                    mma_tf32(s[nt], ah[0], ah[1], ah[2], ah[3], bl0, bl1);
                    mma_tf32(s[nt], al[0], al[1], al[2], al[3], bh0, bh1);
                }
            }
        }
    }
#undef GEMM_LOAD

    // ---- epilogue ----
    const int mA = m0 + 16*warp + g;
    #pragma unroll
    for (int nt = 0; nt < 8; ++nt) {
        const int o = o0 + 8*nt + 2*tg;
        float2 v01 = make_float2(s[nt][0], s[nt][1]);
        float2 v23 = make_float2(s[nt][2], s[nt][3]);
        if (MODE == 0) {
            #pragma unroll
            for (int hf = 0; hf < 2; ++hf) {
                const int m = mA + 8*hf;
                float2 v = hf ? v23 : v01;
                const int b = m >> 12, n = m & 4095;
                if (o < 128) {
                    const int head = o >> 5, hd = o & 31;
                    *(unsigned*)&g_qh[((size_t)(b*HEADS + head)*NSEQ + n)*HD + hd] =
                        bf16x2(v.y*QSCALE, v.x*QSCALE);
                } else if (o < 256) {
                    const int oo = o - 128, head = oo >> 5, hd = oo & 31;
                    *(unsigned*)&g_kh[((size_t)(b*HEADS + head)*NSEQ + n)*HD + hd] =
                        bf16x2(v.y, v.x);
                } else {
                    const int oo = o - 256, head = oo >> 5, hd = oo & 31;
                    unsigned u = bf16x2(v.y, v.x);
                    size_t base = ((size_t)((b*HEADS + head)*128 + (n >> 5))*32 + hd)*32 + (n & 31);
                    g_vT[base]      = (u16)(u & 0xffffu);
                    g_vT[base + 32] = (u16)(u >> 16);
                }
            }
        } else if (MODE == 2) {
            float2 bv = *(const float2*)(bias + o);
            *(float2*)&g_c1[(size_t)mA*C2 + o] =
                make_float2(v01.x + bv.x, v01.y + bv.y);
            *(float2*)&g_c1[(size_t)(mA+8)*C2 + o] =
                make_float2(v23.x + bv.x, v23.y + bv.y);
        } else {
            const float* rs = (MODE == 1) ? resid_ext : g_xmid;
            float*       ds = (MODE == 1) ? g_xmid    : out_ext;
            float2 bv = *(const float2*)(bias + o);
            float2 r0 = *(const float2*)(rs + (size_t)mA*CDIM + o);
            float2 r1 = *(const float2*)(rs + (size_t)(mA+8)*CDIM + o);
            *(float2*)&ds[(size_t)mA*CDIM + o] =
                make_float2(v01.x + bv.x + r0.x, v01.y + bv.y + r0.y);
            *(float2*)&ds[(size_t)(mA+8)*CDIM + o] =
                make_float2(v23.x + bv.x + r1.x, v23.y + bv.y + r1.y);
        }
    }
}

// ---------------- Flash attention: bf16 m16n8k16, split-KV=4, bf16 partials ----------------
__global__ void __launch_bounds__(128, 4) attn_kernel() {
    const int bh    = blockIdx.x;
    const int split = blockIdx.z;
    const int t     = threadIdx.x;
    const int warp  = t >> 5;
    const int lane  = t & 31;
    const int g     = lane >> 2;
    const int tg    = lane & 3;

    const int q0 = blockIdx.y*128 + warp*32;
    const u16* Qb  = g_qh + ((size_t)bh*NSEQ + q0)*HD;
    const u16* Kb  = g_kh + ((size_t)bh*NSEQ + (size_t)split*(NSEQ/SPLITS))*HD;
    const u16* Vtb = g_vT + ((size_t)(bh*128 + split*TILES_PER_SPLIT))*1024;

    unsigned qf[2][2][4];
    #pragma unroll
    for (int mt = 0; mt < 2; ++mt)
        #pragma unroll
        for (int kk = 0; kk < 2; ++kk) {
            qf[mt][kk][0] = *(const unsigned*)&Qb[(16*mt + g    )*HD + 16*kk + 2*tg    ];
            qf[mt][kk][1] = *(const unsigned*)&Qb[(16*mt + g + 8)*HD + 16*kk + 2*tg    ];
            qf[mt][kk][2] = *(const unsigned*)&Qb[(16*mt + g    )*HD + 16*kk + 2*tg + 8];
            qf[mt][kk][3] = *(const unsigned*)&Qb[(16*mt + g + 8)*HD + 16*kk + 2*tg + 8];
        }

    __shared__ u16 Ks[2][32][KP];
    __shared__ u16 Vt[2][32][KP];

    float o[2][4][4] = {};
    float l[4] = {};

    const int lr  = t >> 2;
    const int lc8 = (t & 3) * 8;
    const float4* kptr = (const float4*)Kb  + t;
    const float4* vptr = (const float4*)Vtb + t;

    float4 ka = kptr[0];
    float4 va = vptr[0];

    for (int kt = 0; kt < TILES_PER_SPLIT; ++kt) {
        const int buf = kt & 1;
        *(float4*)&Ks[buf][lr][lc8] = ka;
        *(float4*)&Vt[buf][lr][lc8] = va;
        __syncthreads();

        if (kt + 1 < TILES_PER_SPLIT) {
            ka = kptr[(kt+1)*128];
            va = vptr[(kt+1)*128];
        }

        float s[2][4][4] = {};
        #pragma unroll
        for (int nt = 0; nt < 4; ++nt) {
            #pragma unroll
            for (int kk = 0; kk < 2; ++kk) {
                unsigned b0 = *(const unsigned*)&Ks[buf][8*nt + g][16*kk + 2*tg    ];
                unsigned b1 = *(const unsigned*)&Ks[buf][8*nt + g][16*kk + 2*tg + 8];
                mma_bf16(s[0][nt], qf[0][kk][0], qf[0][kk][1], qf[0][kk][2], qf[0][kk][3], b0, b1);
                mma_bf16(s[1][nt], qf[1][kk][0], qf[1][kk][1], qf[1][kk][2], qf[1][kk][3], b0, b1);
            }
        }

        unsigned pk[2][4][2];
        #pragma unroll
        for (int nt = 0; nt < 4; ++nt)
            #pragma unroll
            for (int mt = 0; mt < 2; ++mt) {
                float e0 = ex2(s[mt][nt][0]);
                float e1 = ex2(s[mt][nt][1]);
                float e2 = ex2(s[mt][nt][2]);
                float e3 = ex2(s[mt][nt][3]);
                l[2*mt]   += e0 + e1;
                l[2*mt+1] += e2 + e3;
                pk[mt][nt][0] = bf16x2(e1, e0);
                pk[mt][nt][1] = bf16x2(e3, e2);
            }

        #pragma unroll
        for (int kk2 = 0; kk2 < 2; ++kk2) {
            #pragma unroll
            for (int nd = 0; nd < 4; ++nd) {
                unsigned b0 = *(const unsigned*)&Vt[buf][8*nd + g][16*kk2 + 2*tg    ];
                unsigned b1 = *(const unsigned*)&Vt[buf][8*nd + g][16*kk2 + 2*tg + 8];
                #pragma unroll
                for (int mt = 0; mt < 2; ++mt)
                    mma_bf16(o[mt][nd],
                             pk[mt][2*kk2][0], pk[mt][2*kk2][1],
                             pk[mt][2*kk2+1][0], pk[mt][2*kk2+1][1],
                             b0, b1);
            }
        }
    }

    #pragma unroll
    for (int i = 0; i < 4; ++i) {
        l[i] += __shfl_xor_sync(0xffffffffu, l[i], 1);
        l[i] += __shfl_xor_sync(0xffffffffu, l[i], 2);
    }

    // write unnormalized partials in bf16
    #pragma unroll
    for (int mt = 0; mt < 2; ++mt) {
        const size_t row = (size_t)bh*NSEQ + q0 + 16*mt + g;
        u16* base0 = g_pacc + ((size_t)split*NROWS + row)*HD;
        u16* base1 = base0 + 8*HD;
        #pragma unroll
        for (int nd = 0; nd < 4; ++nd) {
            *(unsigned*)(base0 + 8*nd + 2*tg) = bf16x2(o[mt][nd][1], o[mt][nd][0]);
            *(unsigned*)(base1 + 8*nd + 2*tg) = bf16x2(o[mt][nd][3], o[mt][nd][2]);
        }
        if (tg == 0) {
            g_pl[(size_t)split*NROWS + row    ] = l[2*mt];
            g_pl[(size_t)split*NROWS + row + 8] = l[2*mt+1];
        }
    }
}

// ---------------- dw 3x3 + 5x5 + gate: spatially tiled, smem halo ----------------
__global__ void __launch_bounds__(256) dw_gate_kernel(const float* __restrict__ w33,
                                                      const float* __restrict__ b33,
                                                      const float* __restrict__ w55,
                                                      const float* __restrict__ b55) {
    __shared__ float sIn[144][64];
    __shared__ float sw3[64][9];
    __shared__ float sw5[64][25];
    __shared__ float sbb[64];

    const int c   = threadIdx.x;
    const int py  = threadIdx.y;
    const int tid = py*32 + c;
    const int ca0 = blockIdx.y * 32;
    const int bz  = blockIdx.z;
    const int ty0 = (blockIdx.x >> 3) * 8;
    const int tx0 = (blockIdx.x & 7) * 8;

    for (int i = tid; i < 64*9; i += 256) {
        int s = i / 9, k = i - s*9;
        int gc = (s < 32) ? (ca0 + s) : (128 + ca0 + s - 32);
        sw3[s][k] = w33[gc*9 + k];
    }
    for (int i = tid; i < 64*25; i += 256) {
        int s = i / 25, k = i - s*25;
        int gc = (s < 32) ? (ca0 + s) : (128 + ca0 + s - 32);
        sw5[s][k] = w55[gc*25 + k];
    }
    if (tid < 64) {
        int gc = (tid < 32) ? (ca0 + tid) : (128 + ca0 + tid - 32);
        sbb[tid] = b33[gc] + b55[gc];
    }

    const float* cbase = g_c1 + (size_t)bz*NSEQ*C2;
    for (int i = tid; i < 2304; i += 256) {
        int px = i >> 4, c4 = i & 15;
        int hy = ty0 + (px/12) - 2, hx = tx0 + (px - (px/12)*12) - 2;
        float4 v = make_float4(0.f, 0.f, 0.f, 0.f);
        if (hy >= 0 && hy < 64 && hx >= 0 && hx < 64) {
            int gc = (c4 < 8) ? (ca0 + c4*4) : (128 + ca0 + (c4-8)*4);
            v = *(const float4*)(cbase + (size_t)(hy*64 + hx)*C2 + gc);
        }
        *(float4*)&sIn[px][c4*4] = v;
    }
    __syncthreads();

    float w5a[25], w5g[25];
    #pragma unroll
    for (int k = 0; k < 25; ++k) { w5a[k] = sw5[c][k]; w5g[k] = sw5[32+c][k]; }
    float w3a[9], w3g[9];
    #pragma unroll
    for (int k = 0; k < 9; ++k)  { w3a[k] = sw3[c][k]; w3g[k] = sw3[32+c][k]; }
    const float ba = sbb[c], bg = sbb[32+c];

    float* gout = g_gate + ((size_t)bz*NSEQ + (ty0+py)*64 + tx0)*CDIM + ca0 + c;

    #pragma unroll
    for (int x = 0; x < 8; ++x) {
        const int p0 = (py+2)*12 + (x+2);
        float a = ba + sIn[p0][c];
        float g = bg + sIn[p0][32+c];
        #pragma unroll
        for (int dy = -2; dy <= 2; ++dy) {
            #pragma unroll
            for (int dx = -2; dx <= 2; ++dx) {
                const int pp = p0 + dy*12 + dx;
                const float va = sIn[pp][c];
                const float vg = sIn[pp][32+c];
                const int i5 = (dy+2)*5 + (dx+2);
                a = fmaf(va, w5a[i5], a);
                g = fmaf(vg, w5g[i5], g);
                if (dy >= -1 && dy <= 1 && dx >= -1 && dx <= 1) {
                    const int i3 = (dy+1)*3 + (dx+1);
                    a = fmaf(va, w3a[i3], a);
                    g = fmaf(vg, w3g[i3], g);
                }
            }
        }
        gout[x*CDIM] = a * g;
    }
}

// ---------------- launch ----------------
extern "C" void kernel_launch(void* const* d_in, const int* in_sizes, int n_in,
                              void* d_out, int out_size) {
    (void)in_sizes; (void)n_in; (void)out_size;
    const float* x       = (const float*)d_in[0];
    const float* ln1_w   = (const float*)d_in[3];
    const float* ln1_b   = (const float*)d_in[4];
    const float* q_w     = (const float*)d_in[5];
    const float* kv_w    = (const float*)d_in[6];
    const float* proj_w  = (const float*)d_in[7];
    const float* proj_b  = (const float*)d_in[8];
    const float* ln2_w   = (const float*)d_in[9];
    const float* ln2_b   = (const float*)d_in[10];
    const float* conv1_w = (const float*)d_in[11];
    const float* conv1_b = (const float*)d_in[12];
    const float* conv33_w= (const float*)d_in[13];
    const float* conv33_b= (const float*)d_in[14];
    const float* conv55_w= (const float*)d_in[15];
    const float* conv55_b= (const float*)d_in[16];
    const float* conv4_w = (const float*)d_in[17];
    const float* conv4_b = (const float*)d_in[18];
    float* out = (float*)d_out;

    // LN1 stats + one-time tf32 weight split (fused)
    ln_stats<1><<<MTOT/8, 256>>>(x, q_w, kv_w, proj_w, conv1_w, conv4_w);        // 0
    gemm_mma<0><<<dim3(128, 6), 128>>>(x, nullptr,
                                       ln1_w, ln1_b, nullptr, nullptr);          // 1
    attn_kernel<<<dim3(8, 32, SPLITS), 128>>>();                                 // 2
    gemm_mma<1><<<dim3(128, 2), 128>>>(nullptr, proj_b,
                                       nullptr, nullptr, x, nullptr);            // 3 (profiled)
    ln_stats<2><<<MTOT/8, 256>>>(nullptr, nullptr, nullptr, nullptr,
                                 nullptr, nullptr);                              // 4
    gemm_mma<2><<<dim3(128, 4), 128>>>(nullptr, conv1_b,
                                       ln2_w, ln2_b, nullptr, nullptr);          // 5
    dw_gate_kernel<<<dim3(64, 4, 2), dim3(32, 8)>>>(conv33_w, conv33_b,
                                                    conv55_w, conv55_b);         // 6
    gemm_mma<3><<<dim3(128, 2), 128>>>(nullptr, conv4_b,
                                       nullptr, nullptr, nullptr, out);          // 7
}